// round 3
// baseline (speedup 1.0000x reference)
#include <cuda_runtime.h>
#include <cuda_bf16.h>
#include <math.h>
#include <stdint.h>

#define NBATCH 32
#define NHEAD  8
#define SEQ    512
#define HD     64

constexpr size_t V_SIZE   = (size_t)NBATCH * SEQ * NHEAD * HD;     // 8388608
constexpr size_t SER_SIZE = (size_t)NBATCH * NHEAD * SEQ * SEQ;    // 67108864

// ---- prepacked fragment arrays (bf16 hi/lo, mma-fragment-major) ----
// KB: [bh 256][stile 64][ktile 4][lane 32]{bhi0,bhi1,blo0,blo1}
// VB: [bh 256][dtile 8][stile 32][lane 32]{bhi0,bhi1,blo0,blo1}
// QA: [bh 256][rtile 32][ktile 4][lane 32]{ahi0..3, alo0..3}
__device__ uint32_t d_KB[(size_t)256 * 64 * 4 * 32 * 4];
__device__ uint32_t d_VB[(size_t)256 * 8 * 32 * 32 * 4];
__device__ uint32_t d_QA[(size_t)256 * 32 * 4 * 32 * 8];

constexpr int KBN = 256 * 64 * 4 * 32;   // 2097152 threads
constexpr int VBN = 256 * 8 * 32 * 32;   // 2097152
constexpr int QAN = 256 * 32 * 4 * 32;   // 1048576
constexpr int PREN = KBN + VBN + QAN;    // 5242880

// smem layout (bytes)
constexpr uint32_t PF_OFF  = 0;          // p-frags: [w8][c2][k2 8][lane32]{4 hi u32, 4 lo u32} = 128KB
constexpr uint32_t RS_OFF  = 131072;     // [2][64] f32 rowsums
constexpr uint32_t INV_OFF = 131584;     // [64] f32
constexpr uint32_t VR_OFF  = 132096;     // [4][8][32] float4 V-reduction = 16KB
constexpr uint32_t SMEM_BYTES = 148480;

__device__ __forceinline__ void packhl(float x0, float x1, uint32_t& hi, uint32_t& lo) {
    __nv_bfloat16 h0 = __float2bfloat16(x0);
    __nv_bfloat16 h1 = __float2bfloat16(x1);
    __nv_bfloat16 l0 = __float2bfloat16(x0 - __bfloat162float(h0));
    __nv_bfloat16 l1 = __float2bfloat16(x1 - __bfloat162float(h1));
    hi = (uint32_t)__bfloat16_as_ushort(h0) | ((uint32_t)__bfloat16_as_ushort(h1) << 16);
    lo = (uint32_t)__bfloat16_as_ushort(l0) | ((uint32_t)__bfloat16_as_ushort(l1) << 16);
}

__device__ __forceinline__ void mma_bf16(float* c, const uint32_t* a, uint32_t b0, uint32_t b1) {
    asm volatile(
        "mma.sync.aligned.m16n8k16.row.col.f32.bf16.bf16.f32 "
        "{%0,%1,%2,%3},{%4,%5,%6,%7},{%8,%9},{%0,%1,%2,%3};\n"
        : "+f"(c[0]), "+f"(c[1]), "+f"(c[2]), "+f"(c[3])
        : "r"(a[0]), "r"(a[1]), "r"(a[2]), "r"(a[3]), "r"(b0), "r"(b1));
}

// ---------------- prepack ----------------
__global__ void __launch_bounds__(256) prepack(const float* __restrict__ Q,
                                               const float* __restrict__ K,
                                               const float* __restrict__ V) {
    int idx = blockIdx.x * 256 + threadIdx.x;
    int lane = idx & 31, g = (idx >> 2) & 7, t = idx & 3;
    uint32_t h0, l0, h1, l1;
    if (idx < KBN) {
        int kt = (idx >> 5) & 3, st = (idx >> 7) & 63, bh = idx >> 13;
        int b = bh >> 3, h = bh & 7;
        int s = st * 8 + g, e0 = kt * 16 + 2 * t;
        const float* kp = K + (((size_t)b * SEQ + s) * NHEAD + h) * HD;
        packhl(kp[e0],     kp[e0 + 1], h0, l0);
        packhl(kp[e0 + 8], kp[e0 + 9], h1, l1);
        *(uint4*)(d_KB + (size_t)idx * 4) = make_uint4(h0, h1, l0, l1);
    } else if (idx < KBN + VBN) {
        int i = idx - KBN;
        int st = (i >> 5) & 31, dt = (i >> 10) & 7, bh = i >> 13;
        int b = bh >> 3, h = bh & 7;
        int s0 = st * 16 + 2 * t, d = dt * 8 + g;
        const float* vp = V + ((size_t)b * SEQ * NHEAD + h) * HD + d;
        packhl(vp[(size_t)s0 * 512],       vp[(size_t)(s0 + 1) * 512], h0, l0);
        packhl(vp[(size_t)(s0 + 8) * 512], vp[(size_t)(s0 + 9) * 512], h1, l1);
        *(uint4*)(d_VB + (size_t)i * 4) = make_uint4(h0, h1, l0, l1);
    } else if (idx < PREN) {
        int i = idx - KBN - VBN;
        int kt = (i >> 5) & 3, rt = (i >> 7) & 31, bh = i >> 12;
        int b = bh >> 3, h = bh & 7;
        int e0 = kt * 16 + 2 * t;
        const float* qp = Q + (((size_t)b * SEQ + rt * 16) * NHEAD + h) * HD;
        uint32_t ah[4], al[4];
        packhl(qp[(size_t)g * 512 + e0],           qp[(size_t)g * 512 + e0 + 1],       ah[0], al[0]);
        packhl(qp[(size_t)(g + 8) * 512 + e0],     qp[(size_t)(g + 8) * 512 + e0 + 1], ah[1], al[1]);
        packhl(qp[(size_t)g * 512 + e0 + 8],       qp[(size_t)g * 512 + e0 + 9],       ah[2], al[2]);
        packhl(qp[(size_t)(g + 8) * 512 + e0 + 8], qp[(size_t)(g + 8) * 512 + e0 + 9], ah[3], al[3]);
        *(uint4*)(d_QA + (size_t)i * 8)     = make_uint4(ah[0], ah[1], ah[2], ah[3]);
        *(uint4*)(d_QA + (size_t)i * 8 + 4) = make_uint4(al[0], al[1], al[2], al[3]);
    }
    (void)lane;
}

// ---------------- main ----------------
__global__ void __launch_bounds__(256) anomaly_mma(const float* __restrict__ SG,
                                                   float* __restrict__ out) {
    extern __shared__ char sm[];
    const int tid = threadIdx.x, lane = tid & 31, wid = tid >> 5;
    const int g = lane >> 2, t = lane & 3;

    const int mt = blockIdx.x & 7;
    const int bh = blockIdx.x >> 3;
    const int h = bh & 7, b = bh >> 3;
    const int l0 = mt * 64;

    const int half = wid >> 2;             // 0: cols 0-255, 1: 256-511
    const int wrb  = (wid & 3) * 16;       // warp row base within 64
    const int rt   = mt * 4 + (wid & 3);   // global row tile

    // Q fragments (hi/lo) for this warp's 16 rows
    uint32_t qhi[4][4], qlo[4][4];
    {
        const uint32_t* qa = d_QA + (((size_t)bh * 32 + rt) * 4 * 32 + lane) * 8;
        #pragma unroll
        for (int kt = 0; kt < 4; kt++) {
            uint4 H = *(const uint4*)(qa + kt * 256);
            uint4 L = *(const uint4*)(qa + kt * 256 + 4);
            qhi[kt][0] = H.x; qhi[kt][1] = H.y; qhi[kt][2] = H.z; qhi[kt][3] = H.w;
            qlo[kt][0] = L.x; qlo[kt][1] = L.y; qlo[kt][2] = L.z; qlo[kt][3] = L.w;
        }
    }

    float vacc[8][4];
    #pragma unroll
    for (int dt = 0; dt < 8; dt++)
        #pragma unroll
        for (int r = 0; r < 4; r++) vacc[dt][r] = 0.f;
    float rs0 = 0.f, rs1 = 0.f;

    // ---- pass A: GEMM1 -> exp -> pack frags -> GEMM2 (unnormalized) ----
    for (int c = 0; c < 2; c++) {
        const int stBase = half * 32 + c * 16;
        #pragma unroll
        for (int k2 = 0; k2 < 8; k2++) {
            float sC[2][4];
            #pragma unroll
            for (int n = 0; n < 2; n++)
                #pragma unroll
                for (int r = 0; r < 4; r++) sC[n][r] = 0.f;

            #pragma unroll
            for (int n = 0; n < 2; n++) {
                const uint32_t* kb = d_KB +
                    (((size_t)bh * 64 + stBase + 2 * k2 + n) * 4 * 32 + lane) * 4;
                #pragma unroll
                for (int kt = 0; kt < 4; kt++) {
                    uint4 Bv = *(const uint4*)(kb + kt * 128);
                    mma_bf16(sC[n], qhi[kt], Bv.x, Bv.y);
                    mma_bf16(sC[n], qhi[kt], Bv.z, Bv.w);
                    mma_bf16(sC[n], qlo[kt], Bv.x, Bv.y);
                }
            }
            #pragma unroll
            for (int n = 0; n < 2; n++)
                #pragma unroll
                for (int r = 0; r < 4; r++) sC[n][r] = __expf(sC[n][r] * 0.125f);
            rs0 += sC[0][0] + sC[0][1] + sC[1][0] + sC[1][1];
            rs1 += sC[0][2] + sC[0][3] + sC[1][2] + sC[1][3];

            // C->A repack (hi/lo split of unnormalized p)
            uint32_t ah[4], al[4];
            packhl(sC[0][0], sC[0][1], ah[0], al[0]);
            packhl(sC[0][2], sC[0][3], ah[1], al[1]);
            packhl(sC[1][0], sC[1][1], ah[2], al[2]);
            packhl(sC[1][2], sC[1][3], ah[3], al[3]);

            uint32_t pfo = PF_OFF + (uint32_t)(((wid * 2 + c) * 8 + k2) * 1024 + lane * 32);
            *(uint4*)(sm + pfo)      = make_uint4(ah[0], ah[1], ah[2], ah[3]);
            *(uint4*)(sm + pfo + 16) = make_uint4(al[0], al[1], al[2], al[3]);

            const int st2 = half * 16 + c * 8 + k2;
            const uint32_t* vb = d_VB + (((size_t)bh * 256 + st2) * 32 + lane) * 4;
            #pragma unroll
            for (int dt = 0; dt < 8; dt++) {
                uint4 Bv = *(const uint4*)(vb + (size_t)dt * 4096);
                mma_bf16(vacc[dt], ah, Bv.x, Bv.y);
                mma_bf16(vacc[dt], ah, Bv.z, Bv.w);
                mma_bf16(vacc[dt], al, Bv.x, Bv.y);
            }
        }
    }

    // ---- rowsums -> inv ----
    rs0 += __shfl_xor_sync(0xffffffffu, rs0, 1);
    rs0 += __shfl_xor_sync(0xffffffffu, rs0, 2);
    rs1 += __shfl_xor_sync(0xffffffffu, rs1, 1);
    rs1 += __shfl_xor_sync(0xffffffffu, rs1, 2);
    float* RS = (float*)(sm + RS_OFF);
    if (t == 0) {
        RS[half * 64 + wrb + g]     = rs0;
        RS[half * 64 + wrb + g + 8] = rs1;
    }
    __syncthreads();
    float* INV = (float*)(sm + INV_OFF);
    if (tid < 64) INV[tid] = 1.0f / (RS[tid] + RS[64 + tid]);
    __syncthreads();

    const float invg  = INV[wrb + g];
    const float invg8 = INV[wrb + g + 8];

    // ---- scale V partials, cross-half reduce, store V ----
    #pragma unroll
    for (int dt = 0; dt < 8; dt++) {
        vacc[dt][0] *= invg;  vacc[dt][1] *= invg;
        vacc[dt][2] *= invg8; vacc[dt][3] *= invg8;
    }
    float4* VR = (float4*)(sm + VR_OFF);
    if (half == 1) {
        #pragma unroll
        for (int dt = 0; dt < 8; dt++)
            VR[((wid & 3) * 8 + dt) * 32 + lane] =
                make_float4(vacc[dt][0], vacc[dt][1], vacc[dt][2], vacc[dt][3]);
    }
    __syncthreads();
    if (half == 0) {
        #pragma unroll
        for (int dt = 0; dt < 8; dt++) {
            float4 p = VR[((wid & 3) * 8 + dt) * 32 + lane];
            float* v0 = out + (((size_t)b * SEQ + l0 + wrb + g) * NHEAD + h) * HD + dt * 8 + 2 * t;
            float* v1 = out + (((size_t)b * SEQ + l0 + wrb + g + 8) * NHEAD + h) * HD + dt * 8 + 2 * t;
            *(float2*)v0 = make_float2(vacc[dt][0] + p.x, vacc[dt][1] + p.y);
            *(float2*)v1 = make_float2(vacc[dt][2] + p.z, vacc[dt][3] + p.w);
        }
    }

    // ---- pass B: series write from stashed frags ----
    float* ser = out + V_SIZE + (((size_t)b * NHEAD + h) * SEQ + l0) * SEQ;
    #pragma unroll
    for (int c = 0; c < 2; c++) {
        #pragma unroll
        for (int k2 = 0; k2 < 8; k2++) {
            uint32_t pfo = PF_OFF + (uint32_t)(((wid * 2 + c) * 8 + k2) * 1024 + lane * 32);
            uint4 H = *(uint4*)(sm + pfo);
            uint4 L = *(uint4*)(sm + pfo + 16);
            const int col = half * 256 + c * 128 + k2 * 16 + 2 * t;
            float* s0p = ser + (size_t)(wrb + g) * SEQ + col;
            float* s1p = ser + (size_t)(wrb + g + 8) * SEQ + col;
            *(float2*)s0p = make_float2(
                (__uint_as_float(H.x << 16) + __uint_as_float(L.x << 16)) * invg,
                (__uint_as_float(H.x & 0xffff0000u) + __uint_as_float(L.x & 0xffff0000u)) * invg);
            *(float2*)s1p = make_float2(
                (__uint_as_float(H.y << 16) + __uint_as_float(L.y << 16)) * invg8,
                (__uint_as_float(H.y & 0xffff0000u) + __uint_as_float(L.y & 0xffff0000u)) * invg8);
            *(float2*)(s0p + 8) = make_float2(
                (__uint_as_float(H.z << 16) + __uint_as_float(L.z << 16)) * invg,
                (__uint_as_float(H.z & 0xffff0000u) + __uint_as_float(L.z & 0xffff0000u)) * invg);
            *(float2*)(s1p + 8) = make_float2(
                (__uint_as_float(H.w << 16) + __uint_as_float(L.w << 16)) * invg8,
                (__uint_as_float(H.w & 0xffff0000u) + __uint_as_float(L.w & 0xffff0000u)) * invg8);
        }
    }

    // ---- prior (8 rows per warp; run-skip underflowed spans) ----
    {
        float amp_ = 0.f, ninv_ = 0.f;
        if (lane < 8) {
            int l = l0 + wid * 8 + lane;
            float x   = SG[((size_t)b * SEQ + l) * NHEAD + h];
            float smv = 1.0f / (1.0f + __expf(-5.0f * x));
            float yf  = smv + 1e-5f;
            float p3  = (float)exp((double)yf * 1.0986122886681098);
            float sig = p3 - 1.0f;
            amp_  = 0.3989422804014327f / sig;
            ninv_ = -1.0f / (2.0f * sig * sig);
        }
        float* priorBase = out + V_SIZE + SER_SIZE + (((size_t)b * NHEAD + h) * SEQ + l0) * SEQ;
        for (int rr = 0; rr < 8; rr++) {
            float amp  = __shfl_sync(0xffffffffu, amp_, rr);
            float ninv = __shfl_sync(0xffffffffu, ninv_, rr);
            const int l = l0 + wid * 8 + rr;
            float* pp = priorBase + (size_t)(wid * 8 + rr) * SEQ;
            const int s0 = lane * 16;
            int dhi = l - s0, dlo = l - (s0 + 15);
            int admin = (dlo <= 0 && dhi >= 0) ? 0 : min(abs(dlo), abs(dhi));
            if (ninv * (float)(admin * admin) < -87.0f) {
                float4 z = make_float4(0.f, 0.f, 0.f, 0.f);
                *(float4*)(pp + s0)      = z;
                *(float4*)(pp + s0 + 4)  = z;
                *(float4*)(pp + s0 + 8)  = z;
                *(float4*)(pp + s0 + 12) = z;
            } else {
                #pragma unroll
                for (int j4 = 0; j4 < 4; j4++) {
                    float d0 = (float)(l - (s0 + j4 * 4 + 0));
                    float d1 = (float)(l - (s0 + j4 * 4 + 1));
                    float d2 = (float)(l - (s0 + j4 * 4 + 2));
                    float d3 = (float)(l - (s0 + j4 * 4 + 3));
                    float4 o;
                    o.x = amp * __expf(ninv * d0 * d0);
                    o.y = amp * __expf(ninv * d1 * d1);
                    o.z = amp * __expf(ninv * d2 * d2);
                    o.w = amp * __expf(ninv * d3 * d3);
                    *(float4*)(pp + s0 + j4 * 4) = o;
                }
            }
        }
    }
}

extern "C" void kernel_launch(void* const* d_in, const int* in_sizes, int n_in,
                              void* d_out, int out_size) {
    (void)in_sizes; (void)n_in; (void)out_size;
    const float* q  = (const float*)d_in[0];
    const float* k  = (const float*)d_in[1];
    const float* v  = (const float*)d_in[2];
    const float* sg = (const float*)d_in[3];
    float* out = (float*)d_out;

    cudaFuncSetAttribute(anomaly_mma, cudaFuncAttributeMaxDynamicSharedMemorySize,
                         (int)SMEM_BYTES);

    prepack<<<PREN / 256, 256>>>(q, k, v);
    anomaly_mma<<<NBATCH * NHEAD * 8, 256, SMEM_BYTES>>>(sg, out);
}

// round 4
// speedup vs baseline: 2.0320x; 2.0320x over previous
#include <cuda_runtime.h>
#include <cuda_bf16.h>
#include <math.h>
#include <stdint.h>

#define NBATCH 32
#define NHEAD  8
#define SEQ    512
#define HD     64

constexpr size_t V_SIZE   = (size_t)NBATCH * SEQ * NHEAD * HD;     // 8388608
constexpr size_t SER_SIZE = (size_t)NBATCH * NHEAD * SEQ * SEQ;    // 67108864

// ---- prepacked fragment arrays (bf16 hi/lo, mma-fragment-major) ----
// KB: [bh 256][stile 64][ktile 4][lane 32]{bhi0,bhi1,blo0,blo1}
// VB: [bh 256][dtile 8][stile 32][lane 32]{bhi0,bhi1,blo0,blo1}
// QA: [bh 256][rtile 32][ktile 4][lane 32]{ahi0..3, alo0..3}
__device__ uint32_t d_KB[(size_t)256 * 64 * 4 * 32 * 4];
__device__ uint32_t d_VB[(size_t)256 * 8 * 32 * 32 * 4];
__device__ uint32_t d_QA[(size_t)256 * 32 * 4 * 32 * 8];

constexpr int KBN = 256 * 64 * 4 * 32;
constexpr int VBN = 256 * 8 * 32 * 32;
constexpr int QAN = 256 * 32 * 4 * 32;
constexpr int PREN = KBN + VBN + QAN;

// ---- smem layout (bytes) ----
// stage: 8 warps x 16 rows x 132 floats = 67584 (reused as V-reduce area later)
constexpr uint32_t STAGE_FLOATS_W = 16 * 132;          // 2112
constexpr uint32_t RS_OFF  = 67584;                    // [4 cq][32 rows] f32
constexpr uint32_t INV_OFF = 68096;                    // [32] f32
constexpr uint32_t SMEM_BYTES = 68224;

__device__ __forceinline__ void packhl(float x0, float x1, uint32_t& hi, uint32_t& lo) {
    __nv_bfloat16 h0 = __float2bfloat16(x0);
    __nv_bfloat16 h1 = __float2bfloat16(x1);
    __nv_bfloat16 l0 = __float2bfloat16(x0 - __bfloat162float(h0));
    __nv_bfloat16 l1 = __float2bfloat16(x1 - __bfloat162float(h1));
    hi = (uint32_t)__bfloat16_as_ushort(h0) | ((uint32_t)__bfloat16_as_ushort(h1) << 16);
    lo = (uint32_t)__bfloat16_as_ushort(l0) | ((uint32_t)__bfloat16_as_ushort(l1) << 16);
}

__device__ __forceinline__ void mma_bf16(float* c, const uint32_t* a, uint32_t b0, uint32_t b1) {
    asm volatile(
        "mma.sync.aligned.m16n8k16.row.col.f32.bf16.bf16.f32 "
        "{%0,%1,%2,%3},{%4,%5,%6,%7},{%8,%9},{%0,%1,%2,%3};\n"
        : "+f"(c[0]), "+f"(c[1]), "+f"(c[2]), "+f"(c[3])
        : "r"(a[0]), "r"(a[1]), "r"(a[2]), "r"(a[3]), "r"(b0), "r"(b1));
}

// ---------------- prepack (unchanged from round 3) ----------------
__global__ void __launch_bounds__(256) prepack(const float* __restrict__ Q,
                                               const float* __restrict__ K,
                                               const float* __restrict__ V) {
    int idx = blockIdx.x * 256 + threadIdx.x;
    int g = (idx >> 2) & 7, t = idx & 3;
    uint32_t h0, l0, h1, l1;
    if (idx < KBN) {
        int kt = (idx >> 5) & 3, st = (idx >> 7) & 63, bh = idx >> 13;
        int b = bh >> 3, h = bh & 7;
        int s = st * 8 + g, e0 = kt * 16 + 2 * t;
        const float* kp = K + (((size_t)b * SEQ + s) * NHEAD + h) * HD;
        packhl(kp[e0],     kp[e0 + 1], h0, l0);
        packhl(kp[e0 + 8], kp[e0 + 9], h1, l1);
        *(uint4*)(d_KB + (size_t)idx * 4) = make_uint4(h0, h1, l0, l1);
    } else if (idx < KBN + VBN) {
        int i = idx - KBN;
        int st = (i >> 5) & 31, dt = (i >> 10) & 7, bh = i >> 13;
        int b = bh >> 3, h = bh & 7;
        int s0 = st * 16 + 2 * t, d = dt * 8 + g;
        const float* vp = V + ((size_t)b * SEQ * NHEAD + h) * HD + d;
        packhl(vp[(size_t)s0 * 512],       vp[(size_t)(s0 + 1) * 512], h0, l0);
        packhl(vp[(size_t)(s0 + 8) * 512], vp[(size_t)(s0 + 9) * 512], h1, l1);
        *(uint4*)(d_VB + (size_t)i * 4) = make_uint4(h0, h1, l0, l1);
    } else if (idx < PREN) {
        int i = idx - KBN - VBN;
        int kt = (i >> 5) & 3, rt = (i >> 7) & 31, bh = i >> 12;
        int b = bh >> 3, h = bh & 7;
        int e0 = kt * 16 + 2 * t;
        const float* qp = Q + (((size_t)b * SEQ + rt * 16) * NHEAD + h) * HD;
        uint32_t ah[4], al[4];
        packhl(qp[(size_t)g * 512 + e0],           qp[(size_t)g * 512 + e0 + 1],       ah[0], al[0]);
        packhl(qp[(size_t)(g + 8) * 512 + e0],     qp[(size_t)(g + 8) * 512 + e0 + 1], ah[1], al[1]);
        packhl(qp[(size_t)g * 512 + e0 + 8],       qp[(size_t)g * 512 + e0 + 9],       ah[2], al[2]);
        packhl(qp[(size_t)(g + 8) * 512 + e0 + 8], qp[(size_t)(g + 8) * 512 + e0 + 9], ah[3], al[3]);
        *(uint4*)(d_QA + (size_t)i * 8)     = make_uint4(ah[0], ah[1], ah[2], ah[3]);
        *(uint4*)(d_QA + (size_t)i * 8 + 4) = make_uint4(al[0], al[1], al[2], al[3]);
    }
}

// ---------------- main ----------------
// CTA: 32 rows x 512 cols of S. 8 warps = 2 row-tiles(16) x 4 col-quarters(128).
__global__ void __launch_bounds__(256, 2) anomaly_mma(const float* __restrict__ SG,
                                                      float* __restrict__ out) {
    extern __shared__ char sm[];
    float* stageAll = (float*)sm;
    float* RS  = (float*)(sm + RS_OFF);
    float* INV = (float*)(sm + INV_OFF);

    const int tid = threadIdx.x, lane = tid & 31, wid = tid >> 5;
    const int g = lane >> 2, t = lane & 3;
    const int mt = blockIdx.x & 15;
    const int bh = blockIdx.x >> 4;
    const int h = bh & 7, b = bh >> 3;
    const int l0 = mt * 32;
    const int rt = wid & 1;        // row-tile within CTA
    const int cq = wid >> 1;       // col-quarter (128 cols)

    // ---- Q fragments for this warp's 16 rows ----
    uint32_t qhi[4][4], qlo[4][4];
    {
        const uint32_t* qa = d_QA + ((size_t)bh * 32 + mt * 2 + rt) * 1024 + (size_t)lane * 8;
        #pragma unroll
        for (int kt = 0; kt < 4; kt++) {
            uint4 H = *(const uint4*)(qa + kt * 256);
            uint4 L = *(const uint4*)(qa + kt * 256 + 4);
            qhi[kt][0] = H.x; qhi[kt][1] = H.y; qhi[kt][2] = H.z; qhi[kt][3] = H.w;
            qlo[kt][0] = L.x; qlo[kt][1] = L.y; qlo[kt][2] = L.z; qlo[kt][3] = L.w;
        }
    }

    float vacc[8][4];
    #pragma unroll
    for (int dt = 0; dt < 8; dt++)
        #pragma unroll
        for (int r = 0; r < 4; r++) vacc[dt][r] = 0.f;
    float rs0 = 0.f, rs1 = 0.f;

    float* stg = stageAll + wid * STAGE_FLOATS_W;

    // ---- pass A: GEMM1 (split accumulators) -> exp -> stage + GEMM2 (unnormalized) ----
    #pragma unroll
    for (int k2 = 0; k2 < 8; k2++) {
        float aH[2][4], aX[2][4];
        #pragma unroll
        for (int n = 0; n < 2; n++)
            #pragma unroll
            for (int r = 0; r < 4; r++) { aH[n][r] = 0.f; aX[n][r] = 0.f; }

        #pragma unroll
        for (int n = 0; n < 2; n++) {
            const int st = cq * 16 + k2 * 2 + n;
            const uint32_t* kb = d_KB + ((size_t)bh * 64 + st) * 512 + (size_t)lane * 4;
            #pragma unroll
            for (int kt = 0; kt < 4; kt++) {
                uint4 Bv = *(const uint4*)(kb + kt * 128);
                mma_bf16(aH[n], qhi[kt], Bv.x, Bv.y);   // hi*hi  (chain depth 4)
                mma_bf16(aX[n], qhi[kt], Bv.z, Bv.w);   // hi*lo  (chain depth 8)
                mma_bf16(aX[n], qlo[kt], Bv.x, Bv.y);   // lo*hi
            }
        }

        float p[2][4];
        #pragma unroll
        for (int n = 0; n < 2; n++)
            #pragma unroll
            for (int r = 0; r < 4; r++)
                p[n][r] = __expf(0.125f * (aH[n][r] + aX[n][r]));

        rs0 += p[0][0] + p[0][1] + p[1][0] + p[1][1];
        rs1 += p[0][2] + p[0][3] + p[1][2] + p[1][3];

        // stage unnormalized fp32 p (row-major, stride 132)
        const int colb = k2 * 16 + 2 * t;
        *(float2*)(stg + g * 132 + colb)           = make_float2(p[0][0], p[0][1]);
        *(float2*)(stg + g * 132 + colb + 8)       = make_float2(p[1][0], p[1][1]);
        *(float2*)(stg + (g + 8) * 132 + colb)     = make_float2(p[0][2], p[0][3]);
        *(float2*)(stg + (g + 8) * 132 + colb + 8) = make_float2(p[1][2], p[1][3]);

        // C->A repack (hi/lo) and GEMM2 accumulate
        uint32_t ah[4], al[4];
        packhl(p[0][0], p[0][1], ah[0], al[0]);
        packhl(p[0][2], p[0][3], ah[1], al[1]);
        packhl(p[1][0], p[1][1], ah[2], al[2]);
        packhl(p[1][2], p[1][3], ah[3], al[3]);

        const int st2 = cq * 8 + k2;
        const uint32_t* vb = d_VB + ((size_t)bh * 256 + st2) * 128 + (size_t)lane * 4;
        #pragma unroll
        for (int dt = 0; dt < 8; dt++) {
            uint4 Bv = *(const uint4*)(vb + (size_t)dt * 4096);
            mma_bf16(vacc[dt], ah, Bv.x, Bv.y);
            mma_bf16(vacc[dt], ah, Bv.z, Bv.w);
            mma_bf16(vacc[dt], al, Bv.x, Bv.y);
        }
    }

    // ---- rowsums -> inv ----
    rs0 += __shfl_xor_sync(0xffffffffu, rs0, 1);
    rs0 += __shfl_xor_sync(0xffffffffu, rs0, 2);
    rs1 += __shfl_xor_sync(0xffffffffu, rs1, 1);
    rs1 += __shfl_xor_sync(0xffffffffu, rs1, 2);
    if (t == 0) {
        RS[cq * 32 + rt * 16 + g]     = rs0;
        RS[cq * 32 + rt * 16 + g + 8] = rs1;
    }
    __syncthreads();
    if (tid < 32) INV[tid] = 1.0f / (RS[tid] + RS[32 + tid] + RS[64 + tid] + RS[96 + tid]);
    __syncthreads();

    // ---- pass B: coalesced series write (512B per row per warp) ----
    float* ser = out + V_SIZE + ((size_t)bh * 512 + l0) * 512;
    #pragma unroll
    for (int r = 0; r < 16; r++) {
        float4 v = *(float4*)(stg + r * 132 + lane * 4);
        const float iv = INV[rt * 16 + r];
        v.x *= iv; v.y *= iv; v.z *= iv; v.w *= iv;
        *(float4*)(ser + (size_t)(rt * 16 + r) * 512 + cq * 128 + lane * 4) = v;
    }
    __syncthreads();   // stage free -> reuse for V reduction

    // ---- V cross-quarter reduction via stage region ----
    {
        const float iv0 = INV[rt * 16 + g];
        const float iv1 = INV[rt * 16 + g + 8];
        float4* VR = (float4*)sm;   // [2 rt][8 dt][32 lane][4 cq]
        #pragma unroll
        for (int dt = 0; dt < 8; dt++)
            VR[(((rt * 8 + dt) * 32) + lane) * 4 + cq] =
                make_float4(vacc[dt][0] * iv0, vacc[dt][1] * iv0,
                            vacc[dt][2] * iv1, vacc[dt][3] * iv1);
        __syncthreads();
        const int rtr = wid & 1, dsel = wid >> 1;
        #pragma unroll
        for (int i = 0; i < 2; i++) {
            const int dt = dsel + i * 4;
            float4 s = make_float4(0.f, 0.f, 0.f, 0.f);
            #pragma unroll
            for (int c = 0; c < 4; c++) {
                float4 pv = VR[(((rtr * 8 + dt) * 32) + lane) * 4 + c];
                s.x += pv.x; s.y += pv.y; s.z += pv.z; s.w += pv.w;
            }
            float* v0 = out + (((size_t)b * SEQ + l0 + rtr * 16 + g) * NHEAD + h) * HD + dt * 8 + 2 * t;
            float* v1 = out + (((size_t)b * SEQ + l0 + rtr * 16 + g + 8) * NHEAD + h) * HD + dt * 8 + 2 * t;
            *(float2*)v0 = make_float2(s.x, s.y);
            *(float2*)v1 = make_float2(s.z, s.w);
        }
    }

    // ---- prior (4 rows per warp; run-skip underflowed spans) ----
    {
        float amp_ = 0.f, ninv_ = 0.f;
        if (lane < 4) {
            int l = l0 + wid * 4 + lane;
            float x   = SG[((size_t)b * SEQ + l) * NHEAD + h];
            float smv = 1.0f / (1.0f + __expf(-5.0f * x));
            float yf  = smv + 1e-5f;
            float p3  = (float)exp((double)yf * 1.0986122886681098);
            float sig = p3 - 1.0f;
            amp_  = 0.3989422804014327f / sig;
            ninv_ = -1.0f / (2.0f * sig * sig);
        }
        float* priorBase = out + V_SIZE + SER_SIZE + ((size_t)bh * 512 + l0) * 512;
        #pragma unroll
        for (int rr = 0; rr < 4; rr++) {
            float amp  = __shfl_sync(0xffffffffu, amp_, rr);
            float ninv = __shfl_sync(0xffffffffu, ninv_, rr);
            const int l = l0 + wid * 4 + rr;
            float* pp = priorBase + (size_t)(wid * 4 + rr) * 512;
            const int s0 = lane * 16;
            int dhi = l - s0, dlo = l - (s0 + 15);
            int admin = (dlo <= 0 && dhi >= 0) ? 0 : min(abs(dlo), abs(dhi));
            if (ninv * (float)(admin * admin) < -87.0f) {
                float4 z = make_float4(0.f, 0.f, 0.f, 0.f);
                *(float4*)(pp + s0)      = z;
                *(float4*)(pp + s0 + 4)  = z;
                *(float4*)(pp + s0 + 8)  = z;
                *(float4*)(pp + s0 + 12) = z;
            } else {
                #pragma unroll
                for (int j4 = 0; j4 < 4; j4++) {
                    float d0 = (float)(l - (s0 + j4 * 4 + 0));
                    float d1 = (float)(l - (s0 + j4 * 4 + 1));
                    float d2 = (float)(l - (s0 + j4 * 4 + 2));
                    float d3 = (float)(l - (s0 + j4 * 4 + 3));
                    float4 o;
                    o.x = amp * __expf(ninv * d0 * d0);
                    o.y = amp * __expf(ninv * d1 * d1);
                    o.z = amp * __expf(ninv * d2 * d2);
                    o.w = amp * __expf(ninv * d3 * d3);
                    *(float4*)(pp + s0 + j4 * 4) = o;
                }
            }
        }
    }
}

extern "C" void kernel_launch(void* const* d_in, const int* in_sizes, int n_in,
                              void* d_out, int out_size) {
    (void)in_sizes; (void)n_in; (void)out_size;
    const float* q  = (const float*)d_in[0];
    const float* k  = (const float*)d_in[1];
    const float* v  = (const float*)d_in[2];
    const float* sg = (const float*)d_in[3];
    float* out = (float*)d_out;

    cudaFuncSetAttribute(anomaly_mma, cudaFuncAttributeMaxDynamicSharedMemorySize,
                         (int)SMEM_BYTES);

    prepack<<<PREN / 256, 256>>>(q, k, v);
    anomaly_mma<<<NBATCH * NHEAD * 16, 256, SMEM_BYTES>>>(sg, out);
}

// round 6
// speedup vs baseline: 2.3068x; 1.1353x over previous
#include <cuda_runtime.h>
#include <cuda_bf16.h>
#include <math.h>
#include <stdint.h>

#define NBATCH 32
#define NHEAD  8
#define SEQ    512
#define HD     64

constexpr size_t V_SIZE   = (size_t)NBATCH * SEQ * NHEAD * HD;     // 8388608
constexpr size_t SER_SIZE = (size_t)NBATCH * NHEAD * SEQ * SEQ;    // 67108864

// ---- prepacked fragment arrays (bf16 hi/lo, mma-fragment-major) ----
__device__ uint32_t d_KB[(size_t)256 * 64 * 4 * 32 * 4];
__device__ uint32_t d_VB[(size_t)256 * 8 * 32 * 32 * 4];
__device__ uint32_t d_QA[(size_t)256 * 32 * 4 * 32 * 8];

constexpr int KBN = 256 * 64 * 4 * 32;
constexpr int VBN = 256 * 8 * 32 * 32;
constexpr int QAN = 256 * 32 * 4 * 32;
constexpr int PREN = KBN + VBN + QAN;

// ---- smem layout (bytes) ----
// A: per-warp 8KB double buffer (K stiles loop1, V stiles loop2); reused as V-partials
//    AFTER a barrier that guarantees all warps exited loop2.
// B: per-warp 4KB P-frag stash [k2 4][part 2][lane 32][16B]
constexpr uint32_t A_OFF  = 0;        // 8 * 8192  = 65536
constexpr uint32_t B_OFF  = 65536;    // 8 * 4096  = 32768
constexpr uint32_t RS_OFF = 98304;    // [16 rows][8 warps] f32 = 512
constexpr uint32_t INV_OFF = 98816;   // [16] f32
constexpr uint32_t SMEM_BYTES = 98944;

__device__ __forceinline__ uint32_t s2u(const void* p) {
    uint32_t a;
    asm("{ .reg .u64 t; cvta.to.shared.u64 t, %1; cvt.u32.u64 %0, t; }" : "=r"(a) : "l"(p));
    return a;
}
__device__ __forceinline__ void cp16(uint32_t dst, const void* src) {
    asm volatile("cp.async.cg.shared.global [%0], [%1], 16;" :: "r"(dst), "l"(src) : "memory");
}
__device__ __forceinline__ void cpcommit() {
    asm volatile("cp.async.commit_group;" ::: "memory");
}
__device__ __forceinline__ void cpwait0() {
    asm volatile("cp.async.wait_group 0;" ::: "memory");
}
__device__ __forceinline__ void cpwait1() {
    asm volatile("cp.async.wait_group 1;" ::: "memory");
}

__device__ __forceinline__ void packhl(float x0, float x1, uint32_t& hi, uint32_t& lo) {
    __nv_bfloat16 h0 = __float2bfloat16(x0);
    __nv_bfloat16 h1 = __float2bfloat16(x1);
    __nv_bfloat16 l0 = __float2bfloat16(x0 - __bfloat162float(h0));
    __nv_bfloat16 l1 = __float2bfloat16(x1 - __bfloat162float(h1));
    hi = (uint32_t)__bfloat16_as_ushort(h0) | ((uint32_t)__bfloat16_as_ushort(h1) << 16);
    lo = (uint32_t)__bfloat16_as_ushort(l0) | ((uint32_t)__bfloat16_as_ushort(l1) << 16);
}

__device__ __forceinline__ void mma_bf16(float* c, const uint32_t* a, uint32_t b0, uint32_t b1) {
    asm volatile(
        "mma.sync.aligned.m16n8k16.row.col.f32.bf16.bf16.f32 "
        "{%0,%1,%2,%3},{%4,%5,%6,%7},{%8,%9},{%0,%1,%2,%3};\n"
        : "+f"(c[0]), "+f"(c[1]), "+f"(c[2]), "+f"(c[3])
        : "r"(a[0]), "r"(a[1]), "r"(a[2]), "r"(a[3]), "r"(b0), "r"(b1));
}

__device__ __forceinline__ float2 serpair(uint32_t Hv, uint32_t Lv, float inv) {
    return make_float2(
        (__uint_as_float(Hv << 16) + __uint_as_float(Lv << 16)) * inv,
        (__uint_as_float(Hv & 0xffff0000u) + __uint_as_float(Lv & 0xffff0000u)) * inv);
}

// ---------------- prepack (unchanged) ----------------
__global__ void __launch_bounds__(256) prepack(const float* __restrict__ Q,
                                               const float* __restrict__ K,
                                               const float* __restrict__ V) {
    int idx = blockIdx.x * 256 + threadIdx.x;
    int g = (idx >> 2) & 7, t = idx & 3;
    uint32_t h0, l0, h1, l1;
    if (idx < KBN) {
        int kt = (idx >> 5) & 3, st = (idx >> 7) & 63, bh = idx >> 13;
        int b = bh >> 3, h = bh & 7;
        int s = st * 8 + g, e0 = kt * 16 + 2 * t;
        const float* kp = K + (((size_t)b * SEQ + s) * NHEAD + h) * HD;
        packhl(kp[e0],     kp[e0 + 1], h0, l0);
        packhl(kp[e0 + 8], kp[e0 + 9], h1, l1);
        *(uint4*)(d_KB + (size_t)idx * 4) = make_uint4(h0, h1, l0, l1);
    } else if (idx < KBN + VBN) {
        int i = idx - KBN;
        int st = (i >> 5) & 31, dt = (i >> 10) & 7, bh = i >> 13;
        int b = bh >> 3, h = bh & 7;
        int s0 = st * 16 + 2 * t, d = dt * 8 + g;
        const float* vp = V + ((size_t)b * SEQ * NHEAD + h) * HD + d;
        packhl(vp[(size_t)s0 * 512],       vp[(size_t)(s0 + 1) * 512], h0, l0);
        packhl(vp[(size_t)(s0 + 8) * 512], vp[(size_t)(s0 + 9) * 512], h1, l1);
        *(uint4*)(d_VB + (size_t)i * 4) = make_uint4(h0, h1, l0, l1);
    } else if (idx < PREN) {
        int i = idx - KBN - VBN;
        int kt = (i >> 5) & 3, rt = (i >> 7) & 31, bh = i >> 12;
        int b = bh >> 3, h = bh & 7;
        int e0 = kt * 16 + 2 * t;
        const float* qp = Q + (((size_t)b * SEQ + rt * 16) * NHEAD + h) * HD;
        uint32_t ah[4], al[4];
        packhl(qp[(size_t)g * 512 + e0],           qp[(size_t)g * 512 + e0 + 1],       ah[0], al[0]);
        packhl(qp[(size_t)(g + 8) * 512 + e0],     qp[(size_t)(g + 8) * 512 + e0 + 1], ah[1], al[1]);
        packhl(qp[(size_t)g * 512 + e0 + 8],       qp[(size_t)g * 512 + e0 + 9],       ah[2], al[2]);
        packhl(qp[(size_t)(g + 8) * 512 + e0 + 8], qp[(size_t)(g + 8) * 512 + e0 + 9], ah[3], al[3]);
        *(uint4*)(d_QA + (size_t)i * 8)     = make_uint4(ah[0], ah[1], ah[2], ah[3]);
        *(uint4*)(d_QA + (size_t)i * 8 + 4) = make_uint4(al[0], al[1], al[2], al[3]);
    }
}

// ---------------- main ----------------
// CTA: 16 rows x 512 cols. 8 warps = 8 col-slices of 64. k2 = 0..3 (16 cols each).
__global__ void __launch_bounds__(256, 2) anomaly_mma(const float* __restrict__ SG,
                                                      float* __restrict__ out) {
    extern __shared__ char sm[];
    const uint32_t smb = s2u(sm);
    float* RS  = (float*)(sm + RS_OFF);
    float* INV = (float*)(sm + INV_OFF);

    const int tid = threadIdx.x, lane = tid & 31, wid = tid >> 5;
    const int g = lane >> 2, t = lane & 3;
    const int mt = blockIdx.x & 31;
    const int bh = blockIdx.x >> 5;
    const int h = bh & 7, b = bh >> 3;
    const int l0 = mt * 16;
    const int cq = wid;

    const uint32_t Aw = smb + A_OFF + wid * 8192;      // double buffer
    char* Awc = sm + A_OFF + wid * 8192;
    char* Bwc = sm + B_OFF + wid * 4096;

    // ---- Q fragments for the CTA's 16 rows (all warps same rows) ----
    uint32_t qhi[4][4], qlo[4][4];
    {
        const uint32_t* qa = d_QA + ((size_t)bh * 32 + mt) * 1024 + (size_t)lane * 8;
        #pragma unroll
        for (int kt = 0; kt < 4; kt++) {
            uint4 H = *(const uint4*)(qa + kt * 256);
            uint4 L = *(const uint4*)(qa + kt * 256 + 4);
            qhi[kt][0] = H.x; qhi[kt][1] = H.y; qhi[kt][2] = H.z; qhi[kt][3] = H.w;
            qlo[kt][0] = L.x; qlo[kt][1] = L.y; qlo[kt][2] = L.z; qlo[kt][3] = L.w;
        }
    }

    const char* srcK = (const char*)d_KB + (size_t)(bh * 64 + cq * 8) * 2048;
    const char* srcV = (const char*)d_VB + (size_t)bh * 131072 + (size_t)cq * 2048;

    // ================= loop1: GEMM1 -> exp -> stash P frags =================
    #pragma unroll
    for (int n = 0; n < 2; n++)
        #pragma unroll
        for (int kt = 0; kt < 4; kt++)
            cp16(Aw + n * 2048 + kt * 512 + lane * 16,
                 srcK + n * 2048 + kt * 512 + lane * 16);
    cpcommit();

    float rs0 = 0.f, rs1 = 0.f;
    #pragma unroll
    for (int k2 = 0; k2 < 4; k2++) {
        if (k2 < 3) {
            const int nb = (k2 + 1) & 1;
            #pragma unroll
            for (int n = 0; n < 2; n++)
                #pragma unroll
                for (int kt = 0; kt < 4; kt++)
                    cp16(Aw + nb * 4096 + n * 2048 + kt * 512 + lane * 16,
                         srcK + (size_t)(k2 + 1) * 4096 + n * 2048 + kt * 512 + lane * 16);
            cpcommit();
            cpwait1();
        } else {
            cpwait0();
        }

        const char* kb = Awc + (k2 & 1) * 4096;
        float aH[2][4], aX[2][4];
        #pragma unroll
        for (int n = 0; n < 2; n++)
            #pragma unroll
            for (int r = 0; r < 4; r++) { aH[n][r] = 0.f; aX[n][r] = 0.f; }

        #pragma unroll
        for (int n = 0; n < 2; n++) {
            #pragma unroll
            for (int kt = 0; kt < 4; kt++) {
                uint4 Bv = *(const uint4*)(kb + n * 2048 + kt * 512 + lane * 16);
                mma_bf16(aH[n], qhi[kt], Bv.x, Bv.y);
                mma_bf16(aX[n], qhi[kt], Bv.z, Bv.w);
                mma_bf16(aX[n], qlo[kt], Bv.x, Bv.y);
            }
        }

        float p[2][4];
        #pragma unroll
        for (int n = 0; n < 2; n++)
            #pragma unroll
            for (int r = 0; r < 4; r++)
                p[n][r] = __expf(0.125f * (aH[n][r] + aX[n][r]));

        rs0 += p[0][0] + p[0][1] + p[1][0] + p[1][1];
        rs1 += p[0][2] + p[0][3] + p[1][2] + p[1][3];

        uint32_t ah[4], al[4];
        packhl(p[0][0], p[0][1], ah[0], al[0]);
        packhl(p[0][2], p[0][3], ah[1], al[1]);
        packhl(p[1][0], p[1][1], ah[2], al[2]);
        packhl(p[1][2], p[1][3], ah[3], al[3]);

        *(uint4*)(Bwc + k2 * 1024 + lane * 16)       = make_uint4(ah[0], ah[1], ah[2], ah[3]);
        *(uint4*)(Bwc + k2 * 1024 + 512 + lane * 16) = make_uint4(al[0], al[1], al[2], al[3]);
    }

    // ---- rowsums -> inv ----
    rs0 += __shfl_xor_sync(0xffffffffu, rs0, 1);
    rs0 += __shfl_xor_sync(0xffffffffu, rs0, 2);
    rs1 += __shfl_xor_sync(0xffffffffu, rs1, 1);
    rs1 += __shfl_xor_sync(0xffffffffu, rs1, 2);
    if (t == 0) {
        RS[g * 8 + wid]       = rs0;
        RS[(g + 8) * 8 + wid] = rs1;
    }
    __syncthreads();
    if (tid < 16) {
        float s = 0.f;
        #pragma unroll
        for (int w = 0; w < 8; w++) s += RS[tid * 8 + w];
        INV[tid] = 1.0f / s;
    }
    __syncthreads();
    const float invg  = INV[g];
    const float invg8 = INV[g + 8];

    // ================= loop2: series stores + GEMM2 =================
    #pragma unroll
    for (int dt = 0; dt < 8; dt++)
        cp16(Aw + dt * 512 + lane * 16, srcV + dt * 16384 + lane * 16);
    cpcommit();

    float vacc[8][4];
    #pragma unroll
    for (int dt = 0; dt < 8; dt++)
        #pragma unroll
        for (int r = 0; r < 4; r++) vacc[dt][r] = 0.f;

    float* ser = out + V_SIZE + ((size_t)bh * 512 + l0) * 512 + cq * 64;

    #pragma unroll
    for (int k2 = 0; k2 < 4; k2++) {
        if (k2 < 3) {
            const int nb = (k2 + 1) & 1;
            #pragma unroll
            for (int dt = 0; dt < 8; dt++)
                cp16(Aw + nb * 4096 + dt * 512 + lane * 16,
                     srcV + (size_t)(k2 + 1) * 512 + dt * 16384 + lane * 16);
            cpcommit();
            cpwait1();
        } else {
            cpwait0();
        }

        uint4 H = *(const uint4*)(Bwc + k2 * 1024 + lane * 16);
        uint4 L = *(const uint4*)(Bwc + k2 * 1024 + 512 + lane * 16);

        // series (normalized, streaming stores; 32B sectors)
        {
            float* r0p = ser + (size_t)g * 512 + k2 * 16 + 2 * t;
            float* r1p = ser + (size_t)(g + 8) * 512 + k2 * 16 + 2 * t;
            __stcs((float2*)r0p,       serpair(H.x, L.x, invg));
            __stcs((float2*)(r0p + 8), serpair(H.z, L.z, invg));
            __stcs((float2*)r1p,       serpair(H.y, L.y, invg8));
            __stcs((float2*)(r1p + 8), serpair(H.w, L.w, invg8));
        }

        // GEMM2 accumulate (unnormalized P)
        const char* vb = Awc + (k2 & 1) * 4096;
        uint32_t ah[4] = {H.x, H.y, H.z, H.w};
        uint32_t al[4] = {L.x, L.y, L.z, L.w};
        #pragma unroll
        for (int dt = 0; dt < 8; dt++) {
            uint4 Bv = *(const uint4*)(vb + dt * 512 + lane * 16);
            mma_bf16(vacc[dt], ah, Bv.x, Bv.y);
            mma_bf16(vacc[dt], ah, Bv.z, Bv.w);
            mma_bf16(vacc[dt], al, Bv.x, Bv.y);
        }
    }

    // ---- V cross-warp reduction (region A reused for partials) ----
    // BARRIER FIRST: all warps must exit loop2 (their cp.async drained by cpwait0)
    // before ANY warp overwrites region A with fp32 partials. Round-5 NaN came
    // from skipping this: partial floats read as bf16 frags -> NaN operands.
    __syncthreads();
    {
        float* part = (float*)(sm + wid * 4096);   // 8 x 4KB inside region A
        #pragma unroll
        for (int dt = 0; dt < 8; dt++) {
            *(float2*)(part + g * 64 + dt * 8 + 2 * t) =
                make_float2(vacc[dt][0] * invg, vacc[dt][1] * invg);
            *(float2*)(part + (g + 8) * 64 + dt * 8 + 2 * t) =
                make_float2(vacc[dt][2] * invg8, vacc[dt][3] * invg8);
        }
        __syncthreads();
        const int d = tid & 63;
        #pragma unroll
        for (int it = 0; it < 4; it++) {
            const int row = (tid >> 6) + it * 4;
            float s = 0.f;
            #pragma unroll
            for (int w = 0; w < 8; w++)
                s += ((float*)(sm + w * 4096))[row * 64 + d];
            __stcs(out + (((size_t)b * SEQ + l0 + row) * NHEAD + h) * HD + d, s);
        }
    }

    // ---- prior (2 rows per warp; run-skip underflowed spans) ----
    {
        float amp_ = 0.f, ninv_ = 0.f;
        if (lane < 2) {
            int l = l0 + wid * 2 + lane;
            float x   = SG[((size_t)b * SEQ + l) * NHEAD + h];
            float smv = 1.0f / (1.0f + __expf(-5.0f * x));
            float yf  = smv + 1e-5f;
            float p3  = (float)exp((double)yf * 1.0986122886681098);
            float sig = p3 - 1.0f;
            amp_  = 0.3989422804014327f / sig;
            ninv_ = -1.0f / (2.0f * sig * sig);
        }
        float* priorBase = out + V_SIZE + SER_SIZE + ((size_t)bh * 512 + l0) * 512;
        #pragma unroll
        for (int rr = 0; rr < 2; rr++) {
            float amp  = __shfl_sync(0xffffffffu, amp_, rr);
            float ninv = __shfl_sync(0xffffffffu, ninv_, rr);
            const int l = l0 + wid * 2 + rr;
            float* pp = priorBase + (size_t)(wid * 2 + rr) * 512;
            const int s0 = lane * 16;
            int dhi = l - s0, dlo = l - (s0 + 15);
            int admin = (dlo <= 0 && dhi >= 0) ? 0 : min(abs(dlo), abs(dhi));
            if (ninv * (float)(admin * admin) < -87.0f) {
                float4 z = make_float4(0.f, 0.f, 0.f, 0.f);
                __stcs((float4*)(pp + s0),      z);
                __stcs((float4*)(pp + s0 + 4),  z);
                __stcs((float4*)(pp + s0 + 8),  z);
                __stcs((float4*)(pp + s0 + 12), z);
            } else {
                #pragma unroll
                for (int j4 = 0; j4 < 4; j4++) {
                    float d0 = (float)(l - (s0 + j4 * 4 + 0));
                    float d1 = (float)(l - (s0 + j4 * 4 + 1));
                    float d2 = (float)(l - (s0 + j4 * 4 + 2));
                    float d3 = (float)(l - (s0 + j4 * 4 + 3));
                    float4 o;
                    o.x = amp * __expf(ninv * d0 * d0);
                    o.y = amp * __expf(ninv * d1 * d1);
                    o.z = amp * __expf(ninv * d2 * d2);
                    o.w = amp * __expf(ninv * d3 * d3);
                    __stcs((float4*)(pp + s0 + j4 * 4), o);
                }
            }
        }
    }
}

extern "C" void kernel_launch(void* const* d_in, const int* in_sizes, int n_in,
                              void* d_out, int out_size) {
    (void)in_sizes; (void)n_in; (void)out_size;
    const float* q  = (const float*)d_in[0];
    const float* k  = (const float*)d_in[1];
    const float* v  = (const float*)d_in[2];
    const float* sg = (const float*)d_in[3];
    float* out = (float*)d_out;

    cudaFuncSetAttribute(anomaly_mma, cudaFuncAttributeMaxDynamicSharedMemorySize,
                         (int)SMEM_BYTES);

    prepack<<<PREN / 256, 256>>>(q, k, v);
    anomaly_mma<<<NBATCH * NHEAD * 32, 256, SMEM_BYTES>>>(sg, out);
}